// round 3
// baseline (speedup 1.0000x reference)
#include <cuda_runtime.h>
#include <math.h>

#define N_NODES 50000
#define N_EDGES 400000
#define N_GRAPHS 512
#define F 32
#define NB 32
#define CUTOFF 5.0f
#define FULL 0xffffffffu

// ---------------- device scratch (no allocations allowed) ----------------
__device__ float g_x0[N_NODES * F];     // x0, later x0' (xprime)
__device__ float g_yacc[N_NODES * F];   // segment-sum accumulator (init to x0 / x0')
__device__ float g_p2[(size_t)N_EDGES * F]; // per-edge Wr_last projection (pass-2 coeffs)
__device__ float g_graph[N_GRAPHS];
__device__ float g_logbinom[NB];

__device__ __forceinline__ float siluf(float x) { return x / (1.f + expf(-x)); }

// ---------------- K0: init x0 = embed[z], yacc = x0, zero graph acc, logbinom ----
__global__ void k_init(const float* __restrict__ embed, const int* __restrict__ z) {
    int i = blockIdx.x * blockDim.x + threadIdx.x;
    if (i < NB) {
        float k = (float)i;
        g_logbinom[i] = lgammaf((float)NB) - lgammaf(k + 1.f) - lgammaf((float)NB - k);
    }
    if (i < N_GRAPHS) g_graph[i] = 0.f;
    if (i < N_NODES * F) {
        int n = i >> 5, f = i & 31;
        float v = embed[z[n] * F + f];
        g_x0[i] = v;
        g_yacc[i] = v;   // y = x + segsum  -> init acc with x0
    }
}

// ---------------- K1: edge pass 1 --------------------------------------------
// warp per edge; lane b computes rbf_b; matvec via shfl broadcast.
// p1 = rbf @ (Wy0[0]+Wx0[0]) used immediately (scatter), p2 = rbf @ Wr_last stored.
__global__ void k_edge1(const float* __restrict__ pos,
                        const int* __restrict__ src, const int* __restrict__ dst,
                        const float* __restrict__ Wy0, const float* __restrict__ Wx0,
                        const float* __restrict__ Wr) {
    __shared__ float W01s[NB][F];
    __shared__ float Wrs[NB][F];
    for (int i = threadIdx.x; i < NB * F; i += blockDim.x) {
        W01s[i >> 5][i & 31] = Wy0[i] + Wx0[i];   // degree-0 blocks are the first NB*F
        Wrs[i >> 5][i & 31]  = Wr[i];
    }
    __syncthreads();

    int lane   = threadIdx.x & 31;
    int warp   = blockIdx.x * (blockDim.x >> 5) + (threadIdx.x >> 5);
    int nwarps = gridDim.x * (blockDim.x >> 5);
    float lb = g_logbinom[lane];
    float kf = (float)lane;

    for (int e = warp; e < N_EDGES; e += nwarps) {
        int s = __ldg(&src[e]);
        int d = __ldg(&dst[e]);
        float dx = __ldg(&pos[s * 3 + 0]) - __ldg(&pos[d * 3 + 0]);
        float dy = __ldg(&pos[s * 3 + 1]) - __ldg(&pos[d * 3 + 1]);
        float dz = __ldg(&pos[s * 3 + 2]) - __ldg(&pos[d * 3 + 2]);
        float r = sqrtf(dx * dx + dy * dy + dz * dz + 1e-12f);
        float t = r * (1.f / CUTOFF);
        if (t >= 1.f) {                       // cutoff -> rbf == 0 exactly
            g_p2[(size_t)e * F + lane] = 0.f;
            continue;
        }
        float fc = expf(1.f - 1.f / fmaxf(1.f - t * t, 1e-7f));
        float u = r / (r + 1.f);
        u = fminf(fmaxf(u, 1e-7f), 1.f - 1e-7f);
        float rbf = expf(lb + kf * logf(u) + ((float)NB - 1.f - kf) * log1pf(-u)) * fc;

        float p1 = 0.f, p2 = 0.f;
#pragma unroll
        for (int b = 0; b < NB; b++) {
            float rb = __shfl_sync(FULL, rbf, b);
            p1 = fmaf(rb, W01s[b][lane], p1);
            p2 = fmaf(rb, Wrs[b][lane], p2);
        }
        g_p2[(size_t)e * F + lane] = p2;
        float msg = p1 * __ldg(&g_x0[s * F + lane]);
        atomicAdd(&g_yacc[d * F + lane], msg);
    }
}

// ---------------- K2: node update 1 (dense->silu->dense, residual) -----------
__global__ void k_node1(const float* __restrict__ W1, const float* __restrict__ b1,
                        const float* __restrict__ W2, const float* __restrict__ b2,
                        const float* __restrict__ c0) {
    __shared__ float W1s[F][F];
    __shared__ float W2s[F][F];
    for (int i = threadIdx.x; i < F * F; i += blockDim.x) {
        W1s[i >> 5][i & 31] = W1[i];
        W2s[i >> 5][i & 31] = W2[i];
    }
    __syncthreads();
    int lane   = threadIdx.x & 31;
    int warp   = blockIdx.x * (blockDim.x >> 5) + (threadIdx.x >> 5);
    int nwarps = gridDim.x * (blockDim.x >> 5);
    float sc  = siluf(__ldg(&c0[0]));
    float bb1 = b1[lane], bb2 = b2[lane];

    for (int n = warp; n < N_NODES; n += nwarps) {
        float y = g_yacc[n * F + lane];
        float y1 = bb1;
#pragma unroll
        for (int f = 0; f < F; f++)
            y1 = fmaf(__shfl_sync(FULL, y, f), W1s[f][lane], y1);
        float g = siluf(y1);          // silu_gate on channel 0 == elementwise silu
        float y2 = bb2;
#pragma unroll
        for (int f = 0; f < F; f++)
            y2 = fmaf(__shfl_sync(FULL, g, f), W2s[f][lane], y2);
        float xp = g_x0[n * F + lane] + sc * y2;
        g_x0[n * F + lane]   = xp;    // x0' for pass 2 gathers
        g_yacc[n * F + lane] = xp;    // init accumulator for y0 = xs0 + segsum
    }
}

// ---------------- K3: edge pass 2 (gather x0', scatter p2*x0') ---------------
__global__ void k_edge2(const int* __restrict__ src, const int* __restrict__ dst) {
    int lane   = threadIdx.x & 31;
    int warp   = blockIdx.x * (blockDim.x >> 5) + (threadIdx.x >> 5);
    int nwarps = gridDim.x * (blockDim.x >> 5);
    for (int e = warp; e < N_EDGES; e += nwarps) {
        float p2 = g_p2[(size_t)e * F + lane];
        if (!__any_sync(FULL, p2 != 0.f)) continue;   // cutoff-dead edge
        int s = __ldg(&src[e]);
        int d = __ldg(&dst[e]);
        float msg = p2 * __ldg(&g_x0[s * F + lane]);
        atomicAdd(&g_yacc[d * F + lane], msg);
    }
}

// ---------------- K4: node update 2 + readout + per-graph scatter ------------
__global__ void k_node2(const float* __restrict__ W11, const float* __restrict__ b11,
                        const float* __restrict__ W21, const float* __restrict__ b21,
                        const float* __restrict__ c1,
                        const float* __restrict__ Wro1, const float* __restrict__ bro1,
                        const float* __restrict__ Wro2, const float* __restrict__ bro2,
                        const float* __restrict__ abias, const int* __restrict__ z,
                        const int* __restrict__ bseg) {
    __shared__ float W11s[F][F];
    __shared__ float W21s[F][F];
    __shared__ float Wro1s[F][F];
    for (int i = threadIdx.x; i < F * F; i += blockDim.x) {
        W11s[i >> 5][i & 31]  = W11[i];
        W21s[i >> 5][i & 31]  = W21[i];
        Wro1s[i >> 5][i & 31] = Wro1[i];
    }
    __syncthreads();
    int lane   = threadIdx.x & 31;
    int warp   = blockIdx.x * (blockDim.x >> 5) + (threadIdx.x >> 5);
    int nwarps = gridDim.x * (blockDim.x >> 5);
    float sc   = siluf(__ldg(&c1[0]));
    float w2c  = Wro2[lane];
    float bb11 = b11[lane], bb21 = b21[lane], bbr = bro1[lane];
    float br2  = __ldg(&bro2[0]);

    for (int n = warp; n < N_NODES; n += nwarps) {
        float y0 = g_yacc[n * F + lane];
        float a = bb11;
#pragma unroll
        for (int f = 0; f < F; f++)
            a = fmaf(__shfl_sync(FULL, y0, f), W11s[f][lane], a);
        a = siluf(a);
        float yb = bb21;
#pragma unroll
        for (int f = 0; f < F; f++)
            yb = fmaf(__shfl_sync(FULL, a, f), W21s[f][lane], yb);
        float xs0 = g_x0[n * F + lane] + sc * yb;
        float h = bbr;
#pragma unroll
        for (int f = 0; f < F; f++)
            h = fmaf(__shfl_sync(FULL, xs0, f), Wro1s[f][lane], h);
        h = siluf(h);
        float part = h * w2c;
#pragma unroll
        for (int off = 16; off; off >>= 1)
            part += __shfl_xor_sync(FULL, part, off);
        if (lane == 0) {
            float ea = part + br2 + __ldg(&abias[z[n]]);
            atomicAdd(&g_graph[bseg[n]], ea);
        }
    }
}

// ---------------- K5: write output (graph_mask is all-true by construction) --
__global__ void k_out(float* __restrict__ out) {
    int g = blockIdx.x * blockDim.x + threadIdx.x;
    if (g < N_GRAPHS) out[g] = g_graph[g];
}

// ---------------- launch ------------------------------------------------------
extern "C" void kernel_launch(void* const* d_in, const int* in_sizes, int n_in,
                              void* d_out, int out_size) {
    const float* positions  = (const float*)d_in[0];
    const float* embed      = (const float*)d_in[1];
    const float* Wy0        = (const float*)d_in[2];
    const float* Wx0        = (const float*)d_in[3];
    const float* W1_0       = (const float*)d_in[4];
    const float* b1_0       = (const float*)d_in[5];
    const float* W2_0       = (const float*)d_in[6];
    const float* b2_0       = (const float*)d_in[7];
    const float* c0         = (const float*)d_in[8];
    const float* Wr_last    = (const float*)d_in[9];
    const float* W1_1       = (const float*)d_in[10];
    const float* b1_1       = (const float*)d_in[11];
    const float* W2_1       = (const float*)d_in[12];
    const float* b2_1       = (const float*)d_in[13];
    const float* c1         = (const float*)d_in[14];
    const float* Wro1       = (const float*)d_in[15];
    const float* bro1       = (const float*)d_in[16];
    const float* Wro2       = (const float*)d_in[17];
    const float* bro2       = (const float*)d_in[18];
    const float* abias      = (const float*)d_in[19];
    const int*   z          = (const int*)d_in[20];
    const int*   dst_idx    = (const int*)d_in[21];
    const int*   src_idx    = (const int*)d_in[22];
    const int*   bseg       = (const int*)d_in[23];
    float*       out        = (float*)d_out;

    k_init<<<(N_NODES * F + 255) / 256, 256>>>(embed, z);
    k_edge1<<<2048, 256>>>(positions, src_idx, dst_idx, Wy0, Wx0, Wr_last);
    k_node1<<<1024, 256>>>(W1_0, b1_0, W2_0, b2_0, c0);
    k_edge2<<<2048, 256>>>(src_idx, dst_idx);
    k_node2<<<1024, 256>>>(W1_1, b1_1, W2_1, b2_1, c1,
                           Wro1, bro1, Wro2, bro2, abias, z, bseg);
    k_out<<<2, 256>>>(out);
}